// round 1
// baseline (speedup 1.0000x reference)
#include <cuda_runtime.h>
#include <math.h>

#define N_NODESC 50000
#define N_EDGESC 800000
#define CCH      128
#define N_GRAPHS 512
#define N_OUTC   5

// ---------------- scratch (device globals: allocation-free) ----------------
__device__ __align__(128) float g_h [N_NODESC * CCH];   // h = x + aggr
__device__ __align__(128) float g_h1[N_NODESC * CCH];   // after first linear
__device__ __align__(128) float g_xo[N_NODESC * CCH];   // layer output
__device__ __align__(128) float g_stats [2 * CCH];      // col sums / sumsq
__device__ __align__(128) float g_affine[2 * CCH];      // BN scale / shift
__device__ __align__(128) float g_pool[N_GRAPHS * CCH]; // max pool

// ---------------- helpers ----------------
__global__ void copy4_kernel(float4* __restrict__ dst, const float4* __restrict__ src, int n) {
    int i = blockIdx.x * blockDim.x + threadIdx.x;
    if (i < n) dst[i] = src[i];
}

__global__ void zero_stats_kernel() {
    g_stats[threadIdx.x] = 0.f;          // 256 threads cover 2*CCH
}

__global__ void zero_pool_kernel() {
    int i = blockIdx.x * blockDim.x + threadIdx.x;
    if (i < N_GRAPHS * CCH) g_pool[i] = 0.f;
}

// ---------------- edge phase: msg = relu(x[src] + w*We + be); h[dst] += msg --
// one warp per edge; each lane handles 4 channels (float4), vec-4 reduction
__global__ void edge_scatter_kernel(const float* __restrict__ x,
                                    const int*   __restrict__ ei,
                                    const float* __restrict__ ew,
                                    const float* __restrict__ We,
                                    const float* __restrict__ be,
                                    float* __restrict__ h) {
    __shared__ float sWe[CCH];
    __shared__ float sbe[CCH];
    int t = threadIdx.x;
    if (t < CCH) sWe[t] = We[t];
    else         sbe[t - CCH] = be[t - CCH];
    __syncthreads();

    int warp = t >> 5;
    int lane = t & 31;
    int e = blockIdx.x * 8 + warp;
    if (e >= N_EDGESC) return;

    int   s = ei[e];
    int   d = ei[N_EDGESC + e];
    float w = ew[e];
    int   c = lane * 4;

    float4 xv = *(const float4*)(x + (size_t)s * CCH + c);
    float4 m;
    m.x = fmaxf(fmaf(w, sWe[c + 0], xv.x) + sbe[c + 0], 0.f);
    m.y = fmaxf(fmaf(w, sWe[c + 1], xv.y) + sbe[c + 1], 0.f);
    m.z = fmaxf(fmaf(w, sWe[c + 2], xv.z) + sbe[c + 2], 0.f);
    m.w = fmaxf(fmaf(w, sWe[c + 3], xv.w) + sbe[c + 3], 0.f);

    float* p = h + (size_t)d * CCH + c;
    asm volatile("red.global.add.v4.f32 [%0], {%1, %2, %3, %4};"
                 :: "l"(p), "f"(m.x), "f"(m.y), "f"(m.z), "f"(m.w)
                 : "memory");
}

// ---------------- GEMM: out[m][n] = sum_k A'[m][k] * W[n][k] + bias[n] ------
// A' = A                         (AFF=false)
// A' = relu(A*scale + shift)     (AFF=true, BN affine + ReLU folded into load)
// out = relu(out)                (RELU=true)
// BM=128, BN=128 (full), BK=8, 256 threads, 8x8 register tile per thread.
template <bool AFF, bool RELU>
__global__ void gemm_nt_kernel(const float* __restrict__ A,
                               const float* __restrict__ W,
                               const float* __restrict__ bias,
                               float* __restrict__ Cmat, int M) {
    __shared__ float sA[8][CCH];
    __shared__ float sB[8][CCH];
    __shared__ float sSc[CCH];
    __shared__ float sSh[CCH];

    int tid = threadIdx.x;
    if (AFF) {
        if (tid < CCH) sSc[tid] = g_affine[tid];
        else           sSh[tid - CCH] = g_affine[tid];
        __syncthreads();
    }

    int m0 = blockIdx.x * 128;
    int lr = tid >> 1;        // 0..127  (row for A load, n for W load)
    int lq = tid & 1;         // which float4 of the 8-wide k slice
    int ty = tid >> 4;        // 0..15 -> m group
    int tx = tid & 15;        // 0..15 -> n group

    float acc[8][8];
#pragma unroll
    for (int i = 0; i < 8; i++)
#pragma unroll
        for (int j = 0; j < 8; j++) acc[i][j] = 0.f;

    for (int k0 = 0; k0 < CCH; k0 += 8) {
        int kb = k0 + lq * 4;
        float4 av = make_float4(0.f, 0.f, 0.f, 0.f);
        int m = m0 + lr;
        if (m < M) av = *(const float4*)(A + (size_t)m * CCH + kb);
        if (AFF) {
            av.x = fmaxf(fmaf(av.x, sSc[kb + 0], sSh[kb + 0]), 0.f);
            av.y = fmaxf(fmaf(av.y, sSc[kb + 1], sSh[kb + 1]), 0.f);
            av.z = fmaxf(fmaf(av.z, sSc[kb + 2], sSh[kb + 2]), 0.f);
            av.w = fmaxf(fmaf(av.w, sSc[kb + 3], sSh[kb + 3]), 0.f);
        }
        int kl = lq * 4;
        sA[kl + 0][lr] = av.x; sA[kl + 1][lr] = av.y;
        sA[kl + 2][lr] = av.z; sA[kl + 3][lr] = av.w;

        float4 wv = *(const float4*)(W + (size_t)lr * CCH + kb);
        sB[kl + 0][lr] = wv.x; sB[kl + 1][lr] = wv.y;
        sB[kl + 2][lr] = wv.z; sB[kl + 3][lr] = wv.w;
        __syncthreads();

#pragma unroll
        for (int kk = 0; kk < 8; kk++) {
            float a[8], b[8];
            *(float4*)&a[0] = *(const float4*)&sA[kk][ty * 8];
            *(float4*)&a[4] = *(const float4*)&sA[kk][ty * 8 + 4];
            *(float4*)&b[0] = *(const float4*)&sB[kk][tx * 8];
            *(float4*)&b[4] = *(const float4*)&sB[kk][tx * 8 + 4];
#pragma unroll
            for (int i = 0; i < 8; i++)
#pragma unroll
                for (int j = 0; j < 8; j++)
                    acc[i][j] = fmaf(a[i], b[j], acc[i][j]);
        }
        __syncthreads();
    }

    float bj[8];
#pragma unroll
    for (int j = 0; j < 8; j++) bj[j] = bias[tx * 8 + j];

#pragma unroll
    for (int i = 0; i < 8; i++) {
        int m = m0 + ty * 8 + i;
        if (m >= M) break;
        float4 v0, v1;
        float v[8];
#pragma unroll
        for (int j = 0; j < 8; j++) {
            float t = acc[i][j] + bj[j];
            if (RELU) t = fmaxf(t, 0.f);
            v[j] = t;
        }
        v0 = make_float4(v[0], v[1], v[2], v[3]);
        v1 = make_float4(v[4], v[5], v[6], v[7]);
        *(float4*)(Cmat + (size_t)m * CCH + tx * 8)     = v0;
        *(float4*)(Cmat + (size_t)m * CCH + tx * 8 + 4) = v1;
    }
}

// ---------------- BN stats (col sum / sumsq over all M rows) ---------------
__global__ void bn_stats_kernel(const float* __restrict__ H, int M) {
    int c  = threadIdx.x;                 // 128 threads
    int r0 = blockIdx.x * 256;
    int r1 = min(r0 + 256, M);
    float s = 0.f, ss = 0.f;
    for (int r = r0; r < r1; r++) {
        float v = H[(size_t)r * CCH + c];
        s += v;
        ss = fmaf(v, v, ss);
    }
    atomicAdd(&g_stats[c], s);
    atomicAdd(&g_stats[CCH + c], ss);
}

__global__ void bn_finalize_kernel(const float* __restrict__ g,
                                   const float* __restrict__ bt, float invN) {
    int c = threadIdx.x;                  // 128 threads
    float mu  = g_stats[c] * invN;
    float var = fmaf(-mu, mu, g_stats[CCH + c] * invN);
    float rs  = rsqrtf(var + 1e-5f);
    float sc  = g[c] * rs;
    g_affine[c]       = sc;
    g_affine[CCH + c] = fmaf(-mu, sc, bt[c]);
}

// ---------------- max pool (values >= 0 after ReLU -> int atomicMax ok) ----
__global__ void pool_max_kernel(const float* __restrict__ X,
                                const int* __restrict__ batch) {
    int node = blockIdx.x * 2 + (threadIdx.x >> 7);
    int c    = threadIdx.x & 127;
    if (node >= N_NODESC) return;
    int b = __ldg(batch + node);
    float v = X[(size_t)node * CCH + c];
    atomicMax((int*)&g_pool[(size_t)b * CCH + c], __float_as_int(v));
}

// ---------------- final linear [512,128] @ [5,128]^T + b -------------------
__global__ void final_linear_kernel(const float* __restrict__ lw,
                                    const float* __restrict__ lb,
                                    float* __restrict__ out) {
    int gph  = blockIdx.x;
    int o    = threadIdx.x >> 5;          // 5 warps
    int lane = threadIdx.x & 31;
    const float* p    = g_pool + (size_t)gph * CCH;
    const float* wrow = lw + (size_t)o * CCH;
    float s = 0.f;
    for (int c = lane; c < CCH; c += 32) s = fmaf(p[c], wrow[c], s);
#pragma unroll
    for (int d = 16; d; d >>= 1) s += __shfl_xor_sync(0xffffffffu, s, d);
    if (lane == 0) out[gph * N_OUTC + o] = s + lb[o];
}

// ---------------- launch ----------------------------------------------------
extern "C" void kernel_launch(void* const* d_in, const int* in_sizes, int n_in,
                              void* d_out, int out_size) {
    const float* x   = (const float*)d_in[0];
    const int*   ei  = (const int*)  d_in[1];
    const float* ew  = (const float*)d_in[2];
    const int*   bat = (const int*)  d_in[3];
    const float* P[18];
    for (int i = 0; i < 18; i++) P[i] = (const float*)d_in[4 + i];
    // P: We0 be0 W1_0 b1_0 g0 bt0 W2_0 b2_0 | We1 be1 W1_1 b1_1 g1 bt1 W2_1 b2_1 | lin_w lin_b
    float* out = (float*)d_out;

    float *ph, *ph1, *pxo;
    cudaGetSymbolAddress((void**)&ph,  g_h);
    cudaGetSymbolAddress((void**)&ph1, g_h1);
    cudaGetSymbolAddress((void**)&pxo, g_xo);

    const int NC4 = N_NODESC * CCH / 4;
    const float invN = 1.f / (float)N_NODESC;

    const float* xin = x;
    for (int l = 0; l < 2; l++) {
        const float* We = P[l * 8 + 0];
        const float* be = P[l * 8 + 1];
        const float* W1 = P[l * 8 + 2];
        const float* b1 = P[l * 8 + 3];
        const float* gg = P[l * 8 + 4];
        const float* bt = P[l * 8 + 5];
        const float* W2 = P[l * 8 + 6];
        const float* b2 = P[l * 8 + 7];

        // h = x  (the "(1+eps)*x" term, eps=0), then scatter-add messages
        copy4_kernel<<<(NC4 + 255) / 256, 256>>>((float4*)ph, (const float4*)xin, NC4);
        zero_stats_kernel<<<1, 256>>>();
        edge_scatter_kernel<<<N_EDGESC / 8, 256>>>(xin, ei, ew, We, be, ph);
        // h1 = h @ W1^T + b1
        gemm_nt_kernel<false, false><<<(N_NODESC + 127) / 128, 256>>>(ph, W1, b1, ph1, N_NODESC);
        // BN stats + affine fold
        bn_stats_kernel<<<(N_NODESC + 255) / 256, 128>>>(ph1, N_NODESC);
        bn_finalize_kernel<<<1, 128>>>(gg, bt, invN);
        // x_out = relu( relu(BN(h1)) @ W2^T + b2 )
        gemm_nt_kernel<true, true><<<(N_NODESC + 127) / 128, 256>>>(ph1, W2, b2, pxo, N_NODESC);
        xin = pxo;
    }

    zero_pool_kernel<<<(N_GRAPHS * CCH + 255) / 256, 256>>>();
    pool_max_kernel<<<N_NODESC / 2, 256>>>(pxo, bat);
    final_linear_kernel<<<N_GRAPHS, 160>>>(P[16], P[17], out);
}